// round 1
// baseline (speedup 1.0000x reference)
#include <cuda_runtime.h>
#include <math.h>

#define NMAX 100000
#define DIN  128
#define HID  16

// ---- scratch (device globals; no allocations allowed) ----
__device__ float g_deg [NMAX];
__device__ float g_dis [NMAX];
__device__ float g_h1  [NMAX * HID];
__device__ float g_agg1[NMAX * HID];
__device__ float g_h2  [NMAX * 2];
__device__ float g_agg2[NMAX * 2];
__device__ int   g_is64;

// edge_index may be int64 (as declared in the reference) or int32 (JAX x64
// disabled). Uniform per-kernel branch on a device flag set by k_detect.
__device__ __forceinline__ long long load_idx(const void* ei, long long pos) {
    return g_is64 ? ((const long long*)ei)[pos]
                  : (long long)((const int*)ei)[pos];
}

__device__ __forceinline__ void red4(float* p, float4 v) {
#if __CUDA_ARCH__ >= 900
    asm volatile("red.global.add.v4.f32 [%0], {%1,%2,%3,%4};"
                 :: "l"(p), "f"(v.x), "f"(v.y), "f"(v.z), "f"(v.w) : "memory");
#else
    atomicAdd(p + 0, v.x); atomicAdd(p + 1, v.y);
    atomicAdd(p + 2, v.z); atomicAdd(p + 3, v.w);
#endif
}

__device__ __forceinline__ void red2(float* p, float2 v) {
#if __CUDA_ARCH__ >= 900
    asm volatile("red.global.add.v2.f32 [%0], {%1,%2};"
                 :: "l"(p), "f"(v.x), "f"(v.y) : "memory");
#else
    atomicAdd(p + 0, v.x); atomicAdd(p + 1, v.y);
#endif
}

// ---- dtype detection: int64 view of int32 data has huge/garbage values ----
__global__ void k_detect(const void* ei, long long e, int n) {
    __shared__ int bad;
    if (threadIdx.x == 0) bad = 0;
    __syncthreads();
    // Only first `e` int64 slots are safe to read even if data is int32
    long long limit = e < 2048 ? e : 2048;
    for (long long i = threadIdx.x; i < limit; i += blockDim.x) {
        long long v = ((const long long*)ei)[i];
        if (v < 0 || v >= n) bad = 1;
    }
    __syncthreads();
    if (threadIdx.x == 0) g_is64 = bad ? 0 : 1;
}

// ---- degree (self-loop baked in as init 1.0) ----
__global__ void k_init_deg(int n) {
    int i = blockIdx.x * blockDim.x + threadIdx.x;
    if (i < n) g_deg[i] = 1.0f;
}

__global__ void k_degree(const void* ei, long long e) {
    long long i = blockIdx.x * (long long)blockDim.x + threadIdx.x;
    if (i >= e) return;
    long long c = load_idx(ei, e + i);   // target
    atomicAdd(&g_deg[c], 1.0f);
}

__global__ void k_dis(int n) {
    int i = blockIdx.x * blockDim.x + threadIdx.x;
    if (i < n) g_dis[i] = rsqrtf(g_deg[i]);
}

// ---- layer 1 transform: h1 = x @ W1 ; agg1 init = self-loop contribution ----
__global__ void k_gemm1(const float* __restrict__ x, const float* __restrict__ W1, int n) {
    __shared__ float sW[DIN * HID];            // 8 KB
    int tid = threadIdx.x;                     // 256 threads = 16 nodes x 16 cols
    for (int i = tid; i < DIN * HID; i += 256) sW[i] = W1[i];
    __syncthreads();
    int gidx = blockIdx.x * 256 + tid;
    int node = gidx / HID;
    int col  = gidx % HID;
    if (node >= n) return;
    const float* xr = x + (long long)node * DIN;
    float acc = 0.f;
#pragma unroll 8
    for (int k = 0; k < DIN; k++) acc += xr[k] * sW[k * HID + col];
    float d = g_dis[node];
    g_h1  [node * HID + col] = acc;
    g_agg1[node * HID + col] = acc * d * d;    // self-loop: norm = dis^2
}

// ---- layer 1 edge scatter: agg1[c] += h1[r] * dis[r]*dis[c] ----
__global__ void k_scatter1(const void* ei, long long e) {
    long long i = blockIdx.x * (long long)blockDim.x + threadIdx.x;
    if (i >= e) return;
    long long r = load_idx(ei, i);
    long long c = load_idx(ei, e + i);
    float nrm = g_dis[r] * g_dis[c];
    const float4* hp = (const float4*)&g_h1[r * HID];
    float* dst = &g_agg1[c * HID];
#pragma unroll
    for (int j = 0; j < 4; j++) {
        float4 v = hp[j];
        v.x *= nrm; v.y *= nrm; v.z *= nrm; v.w *= nrm;
        red4(dst + 4 * j, v);
    }
}

// ---- relu(agg1 + b1), h2 = a @ W2, agg2 init = self-loop contribution ----
__global__ void k_layer2(const float* __restrict__ b1, const float* __restrict__ W2, int n) {
    int i = blockIdx.x * blockDim.x + threadIdx.x;
    if (i >= n) return;
    float a[HID];
    const float4* ag = (const float4*)&g_agg1[(long long)i * HID];
#pragma unroll
    for (int j = 0; j < 4; j++) {
        float4 v = ag[j];
        a[4*j+0] = fmaxf(v.x + __ldg(&b1[4*j+0]), 0.f);
        a[4*j+1] = fmaxf(v.y + __ldg(&b1[4*j+1]), 0.f);
        a[4*j+2] = fmaxf(v.z + __ldg(&b1[4*j+2]), 0.f);
        a[4*j+3] = fmaxf(v.w + __ldg(&b1[4*j+3]), 0.f);
    }
    float h0 = 0.f, h1 = 0.f;
#pragma unroll
    for (int k = 0; k < HID; k++) {
        h0 += a[k] * __ldg(&W2[k * 2 + 0]);
        h1 += a[k] * __ldg(&W2[k * 2 + 1]);
    }
    g_h2[i * 2 + 0] = h0;
    g_h2[i * 2 + 1] = h1;
    float d = g_dis[i];
    float s = d * d;
    g_agg2[i * 2 + 0] = h0 * s;
    g_agg2[i * 2 + 1] = h1 * s;
}

// ---- layer 2 edge scatter ----
__global__ void k_scatter2(const void* ei, long long e) {
    long long i = blockIdx.x * (long long)blockDim.x + threadIdx.x;
    if (i >= e) return;
    long long r = load_idx(ei, i);
    long long c = load_idx(ei, e + i);
    float nrm = g_dis[r] * g_dis[c];
    float2 v = *(const float2*)&g_h2[r * 2];
    v.x *= nrm; v.y *= nrm;
    red2(&g_agg2[c * 2], v);
}

// ---- log_softmax epilogue ----
__global__ void k_out(const float* __restrict__ b2, float* __restrict__ out, int n) {
    int i = blockIdx.x * blockDim.x + threadIdx.x;
    if (i >= n) return;
    float v0 = g_agg2[i * 2 + 0] + __ldg(&b2[0]);
    float v1 = g_agg2[i * 2 + 1] + __ldg(&b2[1]);
    float m  = fmaxf(v0, v1);
    float lse = m + logf(expf(v0 - m) + expf(v1 - m));
    out[i * 2 + 0] = v0 - lse;
    out[i * 2 + 1] = v1 - lse;
}

extern "C" void kernel_launch(void* const* d_in, const int* in_sizes, int n_in,
                              void* d_out, int out_size) {
    const float* x  = (const float*)d_in[0];
    const void*  ei = d_in[1];                 // int64 or int32, detected
    const float* W1 = (const float*)d_in[2];
    const float* b1 = (const float*)d_in[3];
    const float* W2 = (const float*)d_in[4];
    const float* b2 = (const float*)d_in[5];
    float* out = (float*)d_out;

    int n = in_sizes[0] / DIN;                 // 100000
    long long e = (long long)in_sizes[1] / 2;  // 3200000

    int nb_n = (n + 255) / 256;
    int nb_e = (int)((e + 255) / 256);
    int nb_g = (n * HID + 255) / 256;

    k_detect  <<<1, 256>>>(ei, e, n);
    k_init_deg<<<nb_n, 256>>>(n);
    k_degree  <<<nb_e, 256>>>(ei, e);
    k_dis     <<<nb_n, 256>>>(n);
    k_gemm1   <<<nb_g, 256>>>(x, W1, n);
    k_scatter1<<<nb_e, 256>>>(ei, e);
    k_layer2  <<<nb_n, 256>>>(b1, W2, n);
    k_scatter2<<<nb_e, 256>>>(ei, e);
    k_out     <<<nb_n, 256>>>(b2, out, n);
}

// round 2
// speedup vs baseline: 1.1801x; 1.1801x over previous
#include <cuda_runtime.h>
#include <math.h>

#define NMAX 100000
#define EMAX 3200000
#define DIN  128
#define HID  16

// ---- scratch (device globals; allocations forbidden) ----
__device__ float    g_deg [NMAX];
__device__ float    g_dis [NMAX];
__device__ float    g_h1  [NMAX * HID];
__device__ float    g_agg1[NMAX * HID];
__device__ float    g_h2  [NMAX * 2];
__device__ float    g_agg2[NMAX * 2];
__device__ unsigned g_row [EMAX];
__device__ unsigned g_col [EMAX];
__device__ float    g_norm[EMAX];
__device__ int      g_is64;

__device__ __forceinline__ void red4(float* p, float4 v) {
    asm volatile("red.global.add.v4.f32 [%0], {%1,%2,%3,%4};"
                 :: "l"(p), "f"(v.x), "f"(v.y), "f"(v.z), "f"(v.w) : "memory");
}
__device__ __forceinline__ void red2(float* p, float2 v) {
    asm volatile("red.global.add.v2.f32 [%0], {%1,%2};"
                 :: "l"(p), "f"(v.x), "f"(v.y) : "memory");
}

// ---- zero degree (self-loop baked in as 1.0) + dtype detect (block 0) ----
__global__ void k_zero_detect(const void* ei, long long e, int n) {
    int i = blockIdx.x * blockDim.x + threadIdx.x;
    if (i < n) g_deg[i] = 1.0f;
    if (blockIdx.x == 0) {
        __shared__ int bad;
        if (threadIdx.x == 0) bad = 0;
        __syncthreads();
        long long limit = e < 2048 ? e : 2048;   // first e int64 words safe either way
        for (long long j = threadIdx.x; j < limit; j += blockDim.x) {
            long long v = ((const long long*)ei)[j];
            if (v < 0 || v >= n) bad = 1;
        }
        __syncthreads();
        if (threadIdx.x == 0) g_is64 = bad ? 0 : 1;
    }
}

// ---- convert indices to int32 + degree accumulation ----
__global__ void k_prep(const void* __restrict__ ei, long long e) {
    long long i = blockIdx.x * (long long)blockDim.x + threadIdx.x;
    if (i >= e) return;
    unsigned r, c;
    if (g_is64) {
        r = (unsigned)((const long long*)ei)[i];
        c = (unsigned)((const long long*)ei)[e + i];
    } else {
        r = ((const unsigned*)ei)[i];
        c = ((const unsigned*)ei)[e + i];
    }
    g_row[i] = r;
    g_col[i] = c;
    atomicAdd(&g_deg[c], 1.0f);
}

__global__ void k_dis(int n) {
    int i = blockIdx.x * blockDim.x + threadIdx.x;
    if (i < n) g_dis[i] = rsqrtf(g_deg[i]);
}

// ---- h1 = x @ W1 ; agg1 init = self-loop term. 4 threads per node. ----
__global__ void __launch_bounds__(256) k_gemm1(const float* __restrict__ x,
                                               const float* __restrict__ W1, int n) {
    __shared__ float sW[DIN * HID];                    // 8 KB, row-major [k][col]
    int tid = threadIdx.x;
    for (int i = tid; i < DIN * HID; i += 256) sW[i] = W1[i];
    __syncthreads();
    int g    = blockIdx.x * 256 + tid;
    int node = g >> 2;
    int q    = (g & 3) * 4;                            // column group: 0,4,8,12
    if (node >= n) return;
    const float4* xr = (const float4*)(x + (long long)node * DIN);
    float a0 = 0.f, a1 = 0.f, a2 = 0.f, a3 = 0.f;
#pragma unroll
    for (int k4 = 0; k4 < DIN / 4; k4++) {
        float4 xv = xr[k4];
        float4 w0 = *(const float4*)&sW[(k4 * 4 + 0) * HID + q];
        float4 w1 = *(const float4*)&sW[(k4 * 4 + 1) * HID + q];
        float4 w2 = *(const float4*)&sW[(k4 * 4 + 2) * HID + q];
        float4 w3 = *(const float4*)&sW[(k4 * 4 + 3) * HID + q];
        a0 += xv.x * w0.x + xv.y * w1.x + xv.z * w2.x + xv.w * w3.x;
        a1 += xv.x * w0.y + xv.y * w1.y + xv.z * w2.y + xv.w * w3.y;
        a2 += xv.x * w0.z + xv.y * w1.z + xv.z * w2.z + xv.w * w3.z;
        a3 += xv.x * w0.w + xv.y * w1.w + xv.z * w2.w + xv.w * w3.w;
    }
    float d = g_dis[node];
    float s = d * d;
    float4 hv = make_float4(a0, a1, a2, a3);
    *(float4*)&g_h1  [(long long)node * HID + q] = hv;
    *(float4*)&g_agg1[(long long)node * HID + q] =
        make_float4(a0 * s, a1 * s, a2 * s, a3 * s);
}

// ---- layer 1 edge scatter; also caches per-edge norm for layer 2 ----
__global__ void __launch_bounds__(256) k_scatter1(long long e) {
    long long i = blockIdx.x * (long long)blockDim.x + threadIdx.x;
    if (i >= e) return;
    unsigned r = g_row[i], c = g_col[i];
    float nrm = g_dis[r] * g_dis[c];
    g_norm[i] = nrm;
    const float4* hp  = (const float4*)&g_h1[(long long)r * HID];
    float*        dst = &g_agg1[(long long)c * HID];
#pragma unroll
    for (int j = 0; j < 4; j++) {
        float4 v = hp[j];
        v.x *= nrm; v.y *= nrm; v.z *= nrm; v.w *= nrm;
        red4(dst + 4 * j, v);
    }
}

// ---- relu(agg1 + b1) @ W2 ; agg2 init = self-loop term ----
__global__ void k_layer2(const float* __restrict__ b1, const float* __restrict__ W2, int n) {
    int i = blockIdx.x * blockDim.x + threadIdx.x;
    if (i >= n) return;
    float a[HID];
    const float4* ag = (const float4*)&g_agg1[(long long)i * HID];
#pragma unroll
    for (int j = 0; j < 4; j++) {
        float4 v = ag[j];
        a[4*j+0] = fmaxf(v.x + __ldg(&b1[4*j+0]), 0.f);
        a[4*j+1] = fmaxf(v.y + __ldg(&b1[4*j+1]), 0.f);
        a[4*j+2] = fmaxf(v.z + __ldg(&b1[4*j+2]), 0.f);
        a[4*j+3] = fmaxf(v.w + __ldg(&b1[4*j+3]), 0.f);
    }
    float h0 = 0.f, h1 = 0.f;
#pragma unroll
    for (int k = 0; k < HID; k++) {
        h0 += a[k] * __ldg(&W2[k * 2 + 0]);
        h1 += a[k] * __ldg(&W2[k * 2 + 1]);
    }
    g_h2[i * 2 + 0] = h0;
    g_h2[i * 2 + 1] = h1;
    float d = g_dis[i];
    float s = d * d;
    g_agg2[i * 2 + 0] = h0 * s;
    g_agg2[i * 2 + 1] = h1 * s;
}

// ---- layer 2 edge scatter (norm precomputed) ----
__global__ void __launch_bounds__(256) k_scatter2(long long e) {
    long long i = blockIdx.x * (long long)blockDim.x + threadIdx.x;
    if (i >= e) return;
    unsigned r = g_row[i], c = g_col[i];
    float nrm = g_norm[i];
    float2 v = *(const float2*)&g_h2[(long long)r * 2];
    v.x *= nrm; v.y *= nrm;
    red2(&g_agg2[(long long)c * 2], v);
}

// ---- log_softmax epilogue ----
__global__ void k_out(const float* __restrict__ b2, float* __restrict__ out, int n) {
    int i = blockIdx.x * blockDim.x + threadIdx.x;
    if (i >= n) return;
    float v0 = g_agg2[i * 2 + 0] + __ldg(&b2[0]);
    float v1 = g_agg2[i * 2 + 1] + __ldg(&b2[1]);
    float m  = fmaxf(v0, v1);
    float lse = m + logf(expf(v0 - m) + expf(v1 - m));
    out[i * 2 + 0] = v0 - lse;
    out[i * 2 + 1] = v1 - lse;
}

extern "C" void kernel_launch(void* const* d_in, const int* in_sizes, int n_in,
                              void* d_out, int out_size) {
    const float* x  = (const float*)d_in[0];
    const void*  ei = d_in[1];
    const float* W1 = (const float*)d_in[2];
    const float* b1 = (const float*)d_in[3];
    const float* W2 = (const float*)d_in[4];
    const float* b2 = (const float*)d_in[5];
    float* out = (float*)d_out;

    int n = in_sizes[0] / DIN;                 // 100000
    long long e = (long long)in_sizes[1] / 2;  // 3200000

    int nb_n = (n + 255) / 256;
    int nb_e = (int)((e + 255) / 256);
    int nb_g = (n * 4 + 255) / 256;

    k_zero_detect<<<nb_n, 256>>>(ei, e, n);
    k_prep      <<<nb_e, 256>>>(ei, e);
    k_dis       <<<nb_n, 256>>>(n);
    k_gemm1     <<<nb_g, 256>>>(x, W1, n);
    k_scatter1  <<<nb_e, 256>>>(e);
    k_layer2    <<<nb_n, 256>>>(b1, W2, n);
    k_scatter2  <<<nb_e, 256>>>(e);
    k_out       <<<nb_n, 256>>>(b2, out, n);
}

// round 3
// speedup vs baseline: 1.2237x; 1.0370x over previous
#include <cuda_runtime.h>
#include <math.h>

#define NMAX 100000
#define EMAX 3200000
#define DIN  128
#define HID  16

// ---- scratch (device globals; allocations forbidden) ----
__device__ float    g_deg [NMAX];
__device__ float    g_dis [NMAX];
__device__ float    g_h1  [NMAX * HID];
__device__ float    g_agg1[NMAX * HID];
__device__ float    g_h2  [NMAX * 2];
__device__ float    g_agg2[NMAX * 2];
__device__ unsigned g_row [EMAX];
__device__ unsigned g_col [EMAX];
__device__ float    g_norm[EMAX];
__device__ int      g_is64;

__device__ __forceinline__ void red4(float* p, float4 v) {
    asm volatile("red.global.add.v4.f32 [%0], {%1,%2,%3,%4};"
                 :: "l"(p), "f"(v.x), "f"(v.y), "f"(v.z), "f"(v.w) : "memory");
}
__device__ __forceinline__ void red2(float* p, float2 v) {
    asm volatile("red.global.add.v2.f32 [%0], {%1,%2};"
                 :: "l"(p), "f"(v.x), "f"(v.y) : "memory");
}

// ---- zero degree (self-loop baked in as 1.0) + dtype detect (block 0) ----
__global__ void k_zero_detect(const void* ei, long long e, int n) {
    int i = blockIdx.x * blockDim.x + threadIdx.x;
    if (i < n) g_deg[i] = 1.0f;
    if (blockIdx.x == 0) {
        __shared__ int bad;
        if (threadIdx.x == 0) bad = 0;
        __syncthreads();
        long long limit = e < 2048 ? e : 2048;
        for (long long j = threadIdx.x; j < limit; j += blockDim.x) {
            long long v = ((const long long*)ei)[j];
            if (v < 0 || v >= n) bad = 1;
        }
        __syncthreads();
        if (threadIdx.x == 0) g_is64 = bad ? 0 : 1;
    }
}

// ---- convert indices to int32 + degree accumulation ----
__global__ void k_prep(const void* __restrict__ ei, long long e) {
    long long i = blockIdx.x * (long long)blockDim.x + threadIdx.x;
    if (i >= e) return;
    unsigned r, c;
    if (g_is64) {
        r = (unsigned)((const long long*)ei)[i];
        c = (unsigned)((const long long*)ei)[e + i];
    } else {
        r = ((const unsigned*)ei)[i];
        c = ((const unsigned*)ei)[e + i];
    }
    g_row[i] = r;
    g_col[i] = c;
    atomicAdd(&g_deg[c], 1.0f);
}

// ---- h1 = x @ W1 ; dis = rsqrt(deg) fused ; agg1 init = self-loop term ----
// 2 nodes per thread, all 16 cols in registers. One W row (4 uniform LDS.128)
// feeds 32 FMAs -> W wavefronts amortized; each x row loaded exactly once.
__global__ void __launch_bounds__(256) k_gemm1(const float* __restrict__ x,
                                               const float* __restrict__ W1, int n) {
    __shared__ float sW[DIN * HID];            // 8 KB, [k][c]
    int tid = threadIdx.x;
    for (int i = tid; i < DIN * HID; i += 256) sW[i] = W1[i];
    __syncthreads();
    int t  = blockIdx.x * 256 + tid;
    int n0 = t * 2, n1 = t * 2 + 1;
    if (n0 >= n) return;
    bool has1 = (n1 < n);
    const float4* xr0 = (const float4*)(x + (long long)n0 * DIN);
    const float4* xr1 = (const float4*)(x + (long long)(has1 ? n1 : n0) * DIN);

    float aA[HID], aB[HID];
#pragma unroll
    for (int c = 0; c < HID; c++) { aA[c] = 0.f; aB[c] = 0.f; }

#pragma unroll 4
    for (int k4 = 0; k4 < DIN / 4; k4++) {
        float4 xa = xr0[k4];
        float4 xb = xr1[k4];
        float xav[4] = {xa.x, xa.y, xa.z, xa.w};
        float xbv[4] = {xb.x, xb.y, xb.z, xb.w};
#pragma unroll
        for (int j = 0; j < 4; j++) {
            const float4* wr = (const float4*)&sW[(k4 * 4 + j) * HID];
            float4 w0 = wr[0], w1 = wr[1], w2 = wr[2], w3 = wr[3];
            float fa = xav[j], fb = xbv[j];
            aA[0] += fa*w0.x; aA[1] += fa*w0.y; aA[2] += fa*w0.z; aA[3] += fa*w0.w;
            aA[4] += fa*w1.x; aA[5] += fa*w1.y; aA[6] += fa*w1.z; aA[7] += fa*w1.w;
            aA[8] += fa*w2.x; aA[9] += fa*w2.y; aA[10]+= fa*w2.z; aA[11]+= fa*w2.w;
            aA[12]+= fa*w3.x; aA[13]+= fa*w3.y; aA[14]+= fa*w3.z; aA[15]+= fa*w3.w;
            aB[0] += fb*w0.x; aB[1] += fb*w0.y; aB[2] += fb*w0.z; aB[3] += fb*w0.w;
            aB[4] += fb*w1.x; aB[5] += fb*w1.y; aB[6] += fb*w1.z; aB[7] += fb*w1.w;
            aB[8] += fb*w2.x; aB[9] += fb*w2.y; aB[10]+= fb*w2.z; aB[11]+= fb*w2.w;
            aB[12]+= fb*w3.x; aB[13]+= fb*w3.y; aB[14]+= fb*w3.z; aB[15]+= fb*w3.w;
        }
    }

    float d0 = rsqrtf(g_deg[n0]);
    g_dis[n0] = d0;
    float s0 = d0 * d0;
#pragma unroll
    for (int j = 0; j < 4; j++) {
        *(float4*)&g_h1  [(long long)n0 * HID + 4*j] =
            make_float4(aA[4*j], aA[4*j+1], aA[4*j+2], aA[4*j+3]);
        *(float4*)&g_agg1[(long long)n0 * HID + 4*j] =
            make_float4(aA[4*j]*s0, aA[4*j+1]*s0, aA[4*j+2]*s0, aA[4*j+3]*s0);
    }
    if (has1) {
        float d1 = rsqrtf(g_deg[n1]);
        g_dis[n1] = d1;
        float s1 = d1 * d1;
#pragma unroll
        for (int j = 0; j < 4; j++) {
            *(float4*)&g_h1  [(long long)n1 * HID + 4*j] =
                make_float4(aB[4*j], aB[4*j+1], aB[4*j+2], aB[4*j+3]);
            *(float4*)&g_agg1[(long long)n1 * HID + 4*j] =
                make_float4(aB[4*j]*s1, aB[4*j+1]*s1, aB[4*j+2]*s1, aB[4*j+3]*s1);
        }
    }
}

// ---- layer 1 edge scatter; caches per-edge norm for layer 2 ----
__global__ void __launch_bounds__(256) k_scatter1(long long e) {
    long long i = blockIdx.x * (long long)blockDim.x + threadIdx.x;
    if (i >= e) return;
    unsigned r = g_row[i], c = g_col[i];
    float nrm = g_dis[r] * g_dis[c];
    g_norm[i] = nrm;
    const float4* hp  = (const float4*)&g_h1[(long long)r * HID];
    float*        dst = &g_agg1[(long long)c * HID];
#pragma unroll
    for (int j = 0; j < 4; j++) {
        float4 v = hp[j];
        v.x *= nrm; v.y *= nrm; v.z *= nrm; v.w *= nrm;
        red4(dst + 4 * j, v);
    }
}

// ---- relu(agg1 + b1) @ W2 ; agg2 init = self-loop term ----
__global__ void k_layer2(const float* __restrict__ b1, const float* __restrict__ W2, int n) {
    int i = blockIdx.x * blockDim.x + threadIdx.x;
    if (i >= n) return;
    float a[HID];
    const float4* ag = (const float4*)&g_agg1[(long long)i * HID];
#pragma unroll
    for (int j = 0; j < 4; j++) {
        float4 v = ag[j];
        a[4*j+0] = fmaxf(v.x + __ldg(&b1[4*j+0]), 0.f);
        a[4*j+1] = fmaxf(v.y + __ldg(&b1[4*j+1]), 0.f);
        a[4*j+2] = fmaxf(v.z + __ldg(&b1[4*j+2]), 0.f);
        a[4*j+3] = fmaxf(v.w + __ldg(&b1[4*j+3]), 0.f);
    }
    float h0 = 0.f, h1 = 0.f;
#pragma unroll
    for (int k = 0; k < HID; k++) {
        h0 += a[k] * __ldg(&W2[k * 2 + 0]);
        h1 += a[k] * __ldg(&W2[k * 2 + 1]);
    }
    g_h2[i * 2 + 0] = h0;
    g_h2[i * 2 + 1] = h1;
    float d = g_dis[i];
    float s = d * d;
    g_agg2[i * 2 + 0] = h0 * s;
    g_agg2[i * 2 + 1] = h1 * s;
}

// ---- layer 2 edge scatter (norm precomputed) ----
__global__ void __launch_bounds__(256) k_scatter2(long long e) {
    long long i = blockIdx.x * (long long)blockDim.x + threadIdx.x;
    if (i >= e) return;
    unsigned r = g_row[i], c = g_col[i];
    float nrm = g_norm[i];
    float2 v = *(const float2*)&g_h2[(long long)r * 2];
    v.x *= nrm; v.y *= nrm;
    red2(&g_agg2[(long long)c * 2], v);
}

// ---- log_softmax epilogue ----
__global__ void k_out(const float* __restrict__ b2, float* __restrict__ out, int n) {
    int i = blockIdx.x * blockDim.x + threadIdx.x;
    if (i >= n) return;
    float v0 = g_agg2[i * 2 + 0] + __ldg(&b2[0]);
    float v1 = g_agg2[i * 2 + 1] + __ldg(&b2[1]);
    float m  = fmaxf(v0, v1);
    float lse = m + logf(expf(v0 - m) + expf(v1 - m));
    out[i * 2 + 0] = v0 - lse;
    out[i * 2 + 1] = v1 - lse;
}

extern "C" void kernel_launch(void* const* d_in, const int* in_sizes, int n_in,
                              void* d_out, int out_size) {
    const float* x  = (const float*)d_in[0];
    const void*  ei = d_in[1];
    const float* W1 = (const float*)d_in[2];
    const float* b1 = (const float*)d_in[3];
    const float* W2 = (const float*)d_in[4];
    const float* b2 = (const float*)d_in[5];
    float* out = (float*)d_out;

    int n = in_sizes[0] / DIN;                 // 100000
    long long e = (long long)in_sizes[1] / 2;  // 3200000

    int nb_n = (n + 255) / 256;
    int nb_e = (int)((e + 255) / 256);
    int nb_g = ((n + 1) / 2 + 255) / 256;      // 2 nodes per thread

    k_zero_detect<<<nb_n, 256>>>(ei, e, n);
    k_prep      <<<nb_e, 256>>>(ei, e);
    k_gemm1     <<<nb_g, 256>>>(x, W1, n);
    k_scatter1  <<<nb_e, 256>>>(e);
    k_layer2    <<<nb_n, 256>>>(b1, W2, n);
    k_scatter2  <<<nb_e, 256>>>(e);
    k_out       <<<nb_n, 256>>>(b2, out, n);
}

// round 4
// speedup vs baseline: 1.5030x; 1.2282x over previous
#include <cuda_runtime.h>
#include <math.h>

#define NMAX 100000
#define EMAX 3200000
#define DIN  128
#define HID  16
#define SCAN_CHUNK 512
#define MAX_SCAN_BLOCKS 1024

// ---- scratch (device globals; allocations forbidden) ----
__device__ int      g_cnt   [NMAX];     // in-degree (excl self-loop)
__device__ int      g_start [NMAX];     // CSR offsets
__device__ int      g_cursor[NMAX];
__device__ float    g_dis   [NMAX];
__device__ float    g_h1    [NMAX * HID];
__device__ float    g_h2    [NMAX * 2];
__device__ unsigned g_row   [EMAX];
__device__ unsigned g_col   [EMAX];
__device__ unsigned g_srcs  [EMAX];     // CSR: source of each in-edge
__device__ int      g_bsum  [MAX_SCAN_BLOCKS];
__device__ int      g_boff  [MAX_SCAN_BLOCKS];
__device__ int      g_is64;

// ---- block-wide exclusive scan over 256 threads ----
__device__ __forceinline__ int block_exscan256(int v) {
    __shared__ int wsum[8];
    int lane = threadIdx.x & 31, wid = threadIdx.x >> 5;
    int inc = v;
#pragma unroll
    for (int o = 1; o < 32; o <<= 1) {
        int u = __shfl_up_sync(0xffffffffu, inc, o);
        if (lane >= o) inc += u;
    }
    if (lane == 31) wsum[wid] = inc;
    __syncthreads();
    if (wid == 0) {
        int w = (lane < 8) ? wsum[lane] : 0;
        int winc = w;
#pragma unroll
        for (int o = 1; o < 32; o <<= 1) {
            int u = __shfl_up_sync(0xffffffffu, winc, o);
            if (lane >= o) winc += u;
        }
        if (lane < 8) wsum[lane] = winc - w;   // exclusive warp offsets
    }
    __syncthreads();
    return wsum[wid] + inc - v;
}

// ---- zero counts + dtype detect ----
__global__ void k_zero_detect(const void* ei, long long e, int n) {
    int i = blockIdx.x * blockDim.x + threadIdx.x;
    if (i < n) g_cnt[i] = 0;
    if (blockIdx.x == 0) {
        __shared__ int bad;
        if (threadIdx.x == 0) bad = 0;
        __syncthreads();
        long long limit = e < 2048 ? e : 2048;
        for (long long j = threadIdx.x; j < limit; j += blockDim.x) {
            long long v = ((const long long*)ei)[j];
            if (v < 0 || v >= n) bad = 1;
        }
        __syncthreads();
        if (threadIdx.x == 0) g_is64 = bad ? 0 : 1;
    }
}

// ---- convert indices to int32 + degree histogram ----
__global__ void k_prep(const void* __restrict__ ei, long long e) {
    long long i = blockIdx.x * (long long)blockDim.x + threadIdx.x;
    if (i >= e) return;
    unsigned r, c;
    if (g_is64) {
        r = (unsigned)((const long long*)ei)[i];
        c = (unsigned)((const long long*)ei)[e + i];
    } else {
        r = ((const unsigned*)ei)[i];
        c = ((const unsigned*)ei)[e + i];
    }
    g_row[i] = r;
    g_col[i] = c;
    atomicAdd(&g_cnt[c], 1);
}

// ---- scan phase A: per-block sums of g_cnt ----
__global__ void k_scanA(int n) {
    int base = blockIdx.x * SCAN_CHUNK;
    int t = threadIdx.x;
    int i0 = base + 2 * t;
    int s = 0;
    if (i0     < n) s += g_cnt[i0];
    if (i0 + 1 < n) s += g_cnt[i0 + 1];
    __shared__ int sh[8];
    int lane = t & 31, wid = t >> 5;
#pragma unroll
    for (int o = 16; o > 0; o >>= 1) s += __shfl_down_sync(0xffffffffu, s, o);
    if (lane == 0) sh[wid] = s;
    __syncthreads();
    if (t == 0) {
        int tot = 0;
#pragma unroll
        for (int w = 0; w < 8; w++) tot += sh[w];
        g_bsum[blockIdx.x] = tot;
    }
}

// ---- scan phase B: exclusive scan of block sums (single block) ----
__global__ void k_scanB(int nb) {
    int t = threadIdx.x;
    for (int base = 0; base < nb; base += 256) {   // nb <= 256 in practice
        int idx = base + t;
        int v = (idx < nb) ? g_bsum[idx] : 0;
        int ex = block_exscan256(v);
        if (idx < nb) g_boff[idx] = ex;            // nb<=256 -> single pass
    }
}

// ---- scan phase C: per-element exclusive offsets + cursor init ----
__global__ void k_scanC(int n) {
    int base = blockIdx.x * SCAN_CHUNK;
    int t = threadIdx.x;
    int i0 = base + 2 * t;
    int c0 = (i0     < n) ? g_cnt[i0]     : 0;
    int c1 = (i0 + 1 < n) ? g_cnt[i0 + 1] : 0;
    int ex = block_exscan256(c0 + c1) + g_boff[blockIdx.x];
    if (i0 < n)     { g_start[i0]     = ex;      g_cursor[i0]     = ex; }
    if (i0 + 1 < n) { g_start[i0 + 1] = ex + c0; g_cursor[i0 + 1] = ex + c0; }
}

// ---- CSR placement ----
__global__ void __launch_bounds__(256) k_place(long long e) {
    long long i = blockIdx.x * (long long)blockDim.x + threadIdx.x;
    if (i >= e) return;
    unsigned c = g_col[i];
    int pos = atomicAdd(&g_cursor[c], 1);
    g_srcs[pos] = g_row[i];
}

// ---- h1 = x @ W1 ; dis = rsqrt(cnt+1) fused. 2 nodes/thread, 16 cols in regs ----
__global__ void __launch_bounds__(256) k_gemm1(const float* __restrict__ x,
                                               const float* __restrict__ W1, int n) {
    __shared__ float sW[DIN * HID];
    int tid = threadIdx.x;
    for (int i = tid; i < DIN * HID; i += 256) sW[i] = W1[i];
    __syncthreads();
    int t  = blockIdx.x * 256 + tid;
    int n0 = t * 2, n1 = t * 2 + 1;
    if (n0 >= n) return;
    bool has1 = (n1 < n);
    const float4* xr0 = (const float4*)(x + (long long)n0 * DIN);
    const float4* xr1 = (const float4*)(x + (long long)(has1 ? n1 : n0) * DIN);

    float aA[HID], aB[HID];
#pragma unroll
    for (int c = 0; c < HID; c++) { aA[c] = 0.f; aB[c] = 0.f; }

#pragma unroll 4
    for (int k4 = 0; k4 < DIN / 4; k4++) {
        float4 xa = xr0[k4];
        float4 xb = xr1[k4];
        float xav[4] = {xa.x, xa.y, xa.z, xa.w};
        float xbv[4] = {xb.x, xb.y, xb.z, xb.w};
#pragma unroll
        for (int j = 0; j < 4; j++) {
            const float4* wr = (const float4*)&sW[(k4 * 4 + j) * HID];
            float4 w0 = wr[0], w1 = wr[1], w2 = wr[2], w3 = wr[3];
            float fa = xav[j], fb = xbv[j];
            aA[0] += fa*w0.x; aA[1] += fa*w0.y; aA[2] += fa*w0.z; aA[3] += fa*w0.w;
            aA[4] += fa*w1.x; aA[5] += fa*w1.y; aA[6] += fa*w1.z; aA[7] += fa*w1.w;
            aA[8] += fa*w2.x; aA[9] += fa*w2.y; aA[10]+= fa*w2.z; aA[11]+= fa*w2.w;
            aA[12]+= fa*w3.x; aA[13]+= fa*w3.y; aA[14]+= fa*w3.z; aA[15]+= fa*w3.w;
            aB[0] += fb*w0.x; aB[1] += fb*w0.y; aB[2] += fb*w0.z; aB[3] += fb*w0.w;
            aB[4] += fb*w1.x; aB[5] += fb*w1.y; aB[6] += fb*w1.z; aB[7] += fb*w1.w;
            aB[8] += fb*w2.x; aB[9] += fb*w2.y; aB[10]+= fb*w2.z; aB[11]+= fb*w2.w;
            aB[12]+= fb*w3.x; aB[13]+= fb*w3.y; aB[14]+= fb*w3.z; aB[15]+= fb*w3.w;
        }
    }

    g_dis[n0] = rsqrtf((float)(g_cnt[n0] + 1));
#pragma unroll
    for (int j = 0; j < 4; j++)
        *(float4*)&g_h1[(long long)n0 * HID + 4*j] =
            make_float4(aA[4*j], aA[4*j+1], aA[4*j+2], aA[4*j+3]);
    if (has1) {
        g_dis[n1] = rsqrtf((float)(g_cnt[n1] + 1));
#pragma unroll
        for (int j = 0; j < 4; j++)
            *(float4*)&g_h1[(long long)n1 * HID + 4*j] =
                make_float4(aB[4*j], aB[4*j+1], aB[4*j+2], aB[4*j+3]);
    }
}

// ---- layer-1 aggregation (CSR gather) + fused relu/b1/W2 epilogue ----
// 16 lanes per node; lane l owns output column l. No atomics.
__global__ void __launch_bounds__(256) k_agg1(const float* __restrict__ b1,
                                              const float* __restrict__ W2, int n) {
    int t = blockIdx.x * 256 + threadIdx.x;
    int v = t >> 4;
    int l = t & 15;
    bool live = (v < n);
    int vv = live ? v : (n - 1);

    float dv    = g_dis[vv];
    int   start = g_start[vv];
    int   cnt   = g_cnt[vv];
    float acc   = g_h1[(long long)vv * HID + l] * dv * dv;   // self-loop

    int k = 0;
#pragma unroll 2
    for (; k + 2 <= cnt; k += 2) {
        unsigned s0 = g_srcs[start + k];
        unsigned s1 = g_srcs[start + k + 1];
        float n0 = dv * g_dis[s0];
        float n1 = dv * g_dis[s1];
        float h0 = g_h1[(long long)s0 * HID + l];
        float h1v = g_h1[(long long)s1 * HID + l];
        acc += n0 * h0 + n1 * h1v;
    }
    if (k < cnt) {
        unsigned s0 = g_srcs[start + k];
        acc += dv * g_dis[s0] * g_h1[(long long)s0 * HID + l];
    }

    float a  = fmaxf(acc + __ldg(&b1[l]), 0.f);
    float p0 = a * __ldg(&W2[l * 2 + 0]);
    float p1 = a * __ldg(&W2[l * 2 + 1]);
#pragma unroll
    for (int o = 8; o > 0; o >>= 1) {
        p0 += __shfl_down_sync(0xffffffffu, p0, o, 16);
        p1 += __shfl_down_sync(0xffffffffu, p1, o, 16);
    }
    if (live && l == 0) {
        g_h2[(long long)v * 2 + 0] = p0;
        g_h2[(long long)v * 2 + 1] = p1;
    }
}

// ---- layer-2 aggregation (CSR gather) + fused log_softmax output ----
// 8 lanes per node striding over edges.
__global__ void __launch_bounds__(256) k_agg2(const float* __restrict__ b2,
                                              float* __restrict__ out, int n) {
    int t = blockIdx.x * 256 + threadIdx.x;
    int v = t >> 3;
    int l = t & 7;
    bool live = (v < n);
    int vv = live ? v : (n - 1);

    float dv    = g_dis[vv];
    int   start = g_start[vv];
    int   cnt   = g_cnt[vv];
    float a0 = 0.f, a1 = 0.f;
    for (int k = l; k < cnt; k += 8) {
        unsigned s = g_srcs[start + k];
        float nrm = dv * g_dis[s];
        float2 h = *(const float2*)&g_h2[(long long)s * 2];
        a0 += nrm * h.x;
        a1 += nrm * h.y;
    }
#pragma unroll
    for (int o = 4; o > 0; o >>= 1) {
        a0 += __shfl_down_sync(0xffffffffu, a0, o, 8);
        a1 += __shfl_down_sync(0xffffffffu, a1, o, 8);
    }
    if (live && l == 0) {
        float2 hs = *(const float2*)&g_h2[(long long)v * 2];
        a0 += dv * dv * hs.x;
        a1 += dv * dv * hs.y;
        float v0 = a0 + __ldg(&b2[0]);
        float v1 = a1 + __ldg(&b2[1]);
        float m  = fmaxf(v0, v1);
        float lse = m + logf(expf(v0 - m) + expf(v1 - m));
        out[(long long)v * 2 + 0] = v0 - lse;
        out[(long long)v * 2 + 1] = v1 - lse;
    }
}

extern "C" void kernel_launch(void* const* d_in, const int* in_sizes, int n_in,
                              void* d_out, int out_size) {
    const float* x  = (const float*)d_in[0];
    const void*  ei = d_in[1];
    const float* W1 = (const float*)d_in[2];
    const float* b1 = (const float*)d_in[3];
    const float* W2 = (const float*)d_in[4];
    const float* b2 = (const float*)d_in[5];
    float* out = (float*)d_out;

    int n = in_sizes[0] / DIN;                 // 100000
    long long e = (long long)in_sizes[1] / 2;  // 3200000

    int nb_n    = (n + 255) / 256;
    int nb_e    = (int)((e + 255) / 256);
    int nb_scan = (n + SCAN_CHUNK - 1) / SCAN_CHUNK;
    int nb_g    = ((n + 1) / 2 + 255) / 256;
    int nb_a1   = (n * 16 + 255) / 256;
    int nb_a2   = (n * 8 + 255) / 256;

    k_zero_detect<<<nb_n,    256>>>(ei, e, n);
    k_prep       <<<nb_e,    256>>>(ei, e);
    k_scanA      <<<nb_scan, 256>>>(n);
    k_scanB      <<<1,       256>>>(nb_scan);
    k_scanC      <<<nb_scan, 256>>>(n);
    k_place      <<<nb_e,    256>>>(e);
    k_gemm1      <<<nb_g,    256>>>(x, W1, n);
    k_agg1       <<<nb_a1,   256>>>(b1, W2, n);
    k_agg2       <<<nb_a2,   256>>>(b2, out, n);
}

// round 5
// speedup vs baseline: 1.6386x; 1.0902x over previous
#include <cuda_runtime.h>
#include <math.h>

#define NMAX 100000
#define EMAX 3200000
#define DIN  128
#define HID  16
#define SCAN_CHUNK 512
#define MAX_SCAN_BLOCKS 1024

// ---- scratch (device globals; allocations forbidden) ----
__device__ int      g_cnt   [NMAX];
__device__ int      g_start [NMAX];
__device__ int      g_cursor[NMAX];
__device__ float    g_dis   [NMAX];
__device__ float    g_h1    [NMAX * HID];   // PRE-SCALED by dis[node]
__device__ float    g_h2    [NMAX * 2];     // PRE-SCALED by dis[node]
__device__ unsigned g_row   [EMAX];
__device__ unsigned g_col   [EMAX];
__device__ unsigned g_srcs  [EMAX];
__device__ int      g_bsum  [MAX_SCAN_BLOCKS];
__device__ int      g_is64;

__device__ __forceinline__ int block_exscan256(int v) {
    __shared__ int wsum[8];
    int lane = threadIdx.x & 31, wid = threadIdx.x >> 5;
    int inc = v;
#pragma unroll
    for (int o = 1; o < 32; o <<= 1) {
        int u = __shfl_up_sync(0xffffffffu, inc, o);
        if (lane >= o) inc += u;
    }
    if (lane == 31) wsum[wid] = inc;
    __syncthreads();
    if (wid == 0) {
        int w = (lane < 8) ? wsum[lane] : 0;
        int winc = w;
#pragma unroll
        for (int o = 1; o < 32; o <<= 1) {
            int u = __shfl_up_sync(0xffffffffu, winc, o);
            if (lane >= o) winc += u;
        }
        if (lane < 8) wsum[lane] = winc - w;
    }
    __syncthreads();
    return wsum[wid] + inc - v;
}

__global__ void k_zero_detect(const void* ei, long long e, int n) {
    int i = blockIdx.x * blockDim.x + threadIdx.x;
    if (i < n) g_cnt[i] = 0;
    if (blockIdx.x == 0) {
        __shared__ int bad;
        if (threadIdx.x == 0) bad = 0;
        __syncthreads();
        long long limit = e < 2048 ? e : 2048;
        for (long long j = threadIdx.x; j < limit; j += blockDim.x) {
            long long v = ((const long long*)ei)[j];
            if (v < 0 || v >= n) bad = 1;
        }
        __syncthreads();
        if (threadIdx.x == 0) g_is64 = bad ? 0 : 1;
    }
}

__global__ void k_prep(const void* __restrict__ ei, long long e) {
    long long i = blockIdx.x * (long long)blockDim.x + threadIdx.x;
    if (i >= e) return;
    unsigned r, c;
    if (g_is64) {
        r = (unsigned)((const long long*)ei)[i];
        c = (unsigned)((const long long*)ei)[e + i];
    } else {
        r = ((const unsigned*)ei)[i];
        c = ((const unsigned*)ei)[e + i];
    }
    g_row[i] = r;
    g_col[i] = c;
    atomicAdd(&g_cnt[c], 1);
}

// ---- scan A: per-block sums ----
__global__ void k_scanA(int n) {
    int base = blockIdx.x * SCAN_CHUNK;
    int t = threadIdx.x;
    int i0 = base + 2 * t;
    int s = 0;
    if (i0     < n) s += g_cnt[i0];
    if (i0 + 1 < n) s += g_cnt[i0 + 1];
    __shared__ int sh[8];
    int lane = t & 31, wid = t >> 5;
#pragma unroll
    for (int o = 16; o > 0; o >>= 1) s += __shfl_down_sync(0xffffffffu, s, o);
    if (lane == 0) sh[wid] = s;
    __syncthreads();
    if (t == 0) {
        int tot = 0;
#pragma unroll
        for (int w = 0; w < 8; w++) tot += sh[w];
        g_bsum[blockIdx.x] = tot;
    }
}

// ---- scan C: each block computes its own bsum prefix (nb small), then offsets ----
__global__ void k_scanC(int n, int nb) {
    __shared__ int sh[8];
    __shared__ int s_boff;
    int t = threadIdx.x;
    int lane = t & 31, wid = t >> 5;
    // prefix of g_bsum[0..blockIdx.x)
    int p = 0;
    for (int j = t; j < blockIdx.x; j += 256) p += g_bsum[j];
#pragma unroll
    for (int o = 16; o > 0; o >>= 1) p += __shfl_down_sync(0xffffffffu, p, o);
    if (lane == 0) sh[wid] = p;
    __syncthreads();
    if (t == 0) {
        int tot = 0;
#pragma unroll
        for (int w = 0; w < 8; w++) tot += sh[w];
        s_boff = tot;
    }
    __syncthreads();
    int boff = s_boff;
    __syncthreads();                       // sh reused inside block_exscan256

    int base = blockIdx.x * SCAN_CHUNK;
    int i0 = base + 2 * t;
    int c0 = (i0     < n) ? g_cnt[i0]     : 0;
    int c1 = (i0 + 1 < n) ? g_cnt[i0 + 1] : 0;
    int ex = block_exscan256(c0 + c1) + boff;
    if (i0 < n)     { g_start[i0]     = ex;      g_cursor[i0]     = ex; }
    if (i0 + 1 < n) { g_start[i0 + 1] = ex + c0; g_cursor[i0 + 1] = ex + c0; }
}

__global__ void __launch_bounds__(256) k_place(long long e) {
    long long i = blockIdx.x * (long long)blockDim.x + threadIdx.x;
    if (i >= e) return;
    unsigned c = g_col[i];
    int pos = atomicAdd(&g_cursor[c], 1);
    g_srcs[pos] = g_row[i];
}

// ---- h1s = (x @ W1) * dis ; dis = rsqrt(cnt+1) fused ----
__global__ void __launch_bounds__(256) k_gemm1(const float* __restrict__ x,
                                               const float* __restrict__ W1, int n) {
    __shared__ float sW[DIN * HID];
    int tid = threadIdx.x;
    for (int i = tid; i < DIN * HID; i += 256) sW[i] = W1[i];
    __syncthreads();
    int t  = blockIdx.x * 256 + tid;
    int n0 = t * 2, n1 = t * 2 + 1;
    if (n0 >= n) return;
    bool has1 = (n1 < n);
    const float4* xr0 = (const float4*)(x + (long long)n0 * DIN);
    const float4* xr1 = (const float4*)(x + (long long)(has1 ? n1 : n0) * DIN);

    float aA[HID], aB[HID];
#pragma unroll
    for (int c = 0; c < HID; c++) { aA[c] = 0.f; aB[c] = 0.f; }

#pragma unroll 4
    for (int k4 = 0; k4 < DIN / 4; k4++) {
        float4 xa = xr0[k4];
        float4 xb = xr1[k4];
        float xav[4] = {xa.x, xa.y, xa.z, xa.w};
        float xbv[4] = {xb.x, xb.y, xb.z, xb.w};
#pragma unroll
        for (int j = 0; j < 4; j++) {
            const float4* wr = (const float4*)&sW[(k4 * 4 + j) * HID];
            float4 w0 = wr[0], w1 = wr[1], w2 = wr[2], w3 = wr[3];
            float fa = xav[j], fb = xbv[j];
            aA[0] += fa*w0.x; aA[1] += fa*w0.y; aA[2] += fa*w0.z; aA[3] += fa*w0.w;
            aA[4] += fa*w1.x; aA[5] += fa*w1.y; aA[6] += fa*w1.z; aA[7] += fa*w1.w;
            aA[8] += fa*w2.x; aA[9] += fa*w2.y; aA[10]+= fa*w2.z; aA[11]+= fa*w2.w;
            aA[12]+= fa*w3.x; aA[13]+= fa*w3.y; aA[14]+= fa*w3.z; aA[15]+= fa*w3.w;
            aB[0] += fb*w0.x; aB[1] += fb*w0.y; aB[2] += fb*w0.z; aB[3] += fb*w0.w;
            aB[4] += fb*w1.x; aB[5] += fb*w1.y; aB[6] += fb*w1.z; aB[7] += fb*w1.w;
            aB[8] += fb*w2.x; aB[9] += fb*w2.y; aB[10]+= fb*w2.z; aB[11]+= fb*w2.w;
            aB[12]+= fb*w3.x; aB[13]+= fb*w3.y; aB[14]+= fb*w3.z; aB[15]+= fb*w3.w;
        }
    }

    float d0 = rsqrtf((float)(g_cnt[n0] + 1));
    g_dis[n0] = d0;
#pragma unroll
    for (int j = 0; j < 4; j++)
        *(float4*)&g_h1[(long long)n0 * HID + 4*j] =
            make_float4(aA[4*j]*d0, aA[4*j+1]*d0, aA[4*j+2]*d0, aA[4*j+3]*d0);
    if (has1) {
        float d1 = rsqrtf((float)(g_cnt[n1] + 1));
        g_dis[n1] = d1;
#pragma unroll
        for (int j = 0; j < 4; j++)
            *(float4*)&g_h1[(long long)n1 * HID + 4*j] =
                make_float4(aB[4*j]*d1, aB[4*j+1]*d1, aB[4*j+2]*d1, aB[4*j+3]*d1);
    }
}

// ---- layer-1 aggregation: out = dv*(Sum h1s[src] + h1s[v]); fused relu/b1/W2;
//      writes h2 PRE-SCALED by dv. 16 lanes/node, pure-add inner loop, unroll 4.
__global__ void __launch_bounds__(256) k_agg1(const float* __restrict__ b1,
                                              const float* __restrict__ W2, int n) {
    int t = blockIdx.x * 256 + threadIdx.x;
    int v = t >> 4;
    int l = t & 15;
    bool live = (v < n);
    int vv = live ? v : (n - 1);

    float dv    = g_dis[vv];
    int   start = g_start[vv];
    int   cnt   = g_cnt[vv];

    float a0 = g_h1[(long long)vv * HID + l];   // self term (already * dv)
    float a1 = 0.f, a2 = 0.f, a3 = 0.f;
    int k = 0;
    for (; k + 4 <= cnt; k += 4) {
        unsigned s0 = g_srcs[start + k];
        unsigned s1 = g_srcs[start + k + 1];
        unsigned s2 = g_srcs[start + k + 2];
        unsigned s3 = g_srcs[start + k + 3];
        a0 += g_h1[(long long)s0 * HID + l];
        a1 += g_h1[(long long)s1 * HID + l];
        a2 += g_h1[(long long)s2 * HID + l];
        a3 += g_h1[(long long)s3 * HID + l];
    }
    for (; k < cnt; k++) {
        unsigned s = g_srcs[start + k];
        a0 += g_h1[(long long)s * HID + l];
    }
    float acc = dv * ((a0 + a1) + (a2 + a3));

    float a  = fmaxf(acc + __ldg(&b1[l]), 0.f);
    float p0 = a * __ldg(&W2[l * 2 + 0]);
    float p1 = a * __ldg(&W2[l * 2 + 1]);
#pragma unroll
    for (int o = 8; o > 0; o >>= 1) {
        p0 += __shfl_down_sync(0xffffffffu, p0, o, 16);
        p1 += __shfl_down_sync(0xffffffffu, p1, o, 16);
    }
    if (live && l == 0) {
        g_h2[(long long)v * 2 + 0] = p0 * dv;   // pre-scale for layer 2
        g_h2[(long long)v * 2 + 1] = p1 * dv;
    }
}

// ---- layer-2 aggregation + fused log_softmax. 8 lanes/node. ----
__global__ void __launch_bounds__(256) k_agg2(const float* __restrict__ b2,
                                              float* __restrict__ out, int n) {
    int t = blockIdx.x * 256 + threadIdx.x;
    int v = t >> 3;
    int l = t & 7;
    bool live = (v < n);
    int vv = live ? v : (n - 1);

    float dv    = g_dis[vv];
    int   start = g_start[vv];
    int   cnt   = g_cnt[vv];
    float a0 = 0.f, a1 = 0.f, b0 = 0.f, b1v = 0.f;
    int k = l;
    for (; k + 8 < cnt; k += 16) {
        unsigned s0 = g_srcs[start + k];
        unsigned s1 = g_srcs[start + k + 8];
        float2 h0 = *(const float2*)&g_h2[(long long)s0 * 2];
        float2 h1 = *(const float2*)&g_h2[(long long)s1 * 2];
        a0 += h0.x; a1 += h0.y;
        b0 += h1.x; b1v += h1.y;
    }
    if (k < cnt) {
        unsigned s = g_srcs[start + k];
        float2 h = *(const float2*)&g_h2[(long long)s * 2];
        a0 += h.x; a1 += h.y;
    }
    a0 += b0; a1 += b1v;
#pragma unroll
    for (int o = 4; o > 0; o >>= 1) {
        a0 += __shfl_down_sync(0xffffffffu, a0, o, 8);
        a1 += __shfl_down_sync(0xffffffffu, a1, o, 8);
    }
    if (live && l == 0) {
        float2 hs = *(const float2*)&g_h2[(long long)v * 2];
        float v0 = dv * (a0 + hs.x) + __ldg(&b2[0]);
        float v1 = dv * (a1 + hs.y) + __ldg(&b2[1]);
        float m  = fmaxf(v0, v1);
        float lse = m + logf(expf(v0 - m) + expf(v1 - m));
        out[(long long)v * 2 + 0] = v0 - lse;
        out[(long long)v * 2 + 1] = v1 - lse;
    }
}

extern "C" void kernel_launch(void* const* d_in, const int* in_sizes, int n_in,
                              void* d_out, int out_size) {
    const float* x  = (const float*)d_in[0];
    const void*  ei = d_in[1];
    const float* W1 = (const float*)d_in[2];
    const float* b1 = (const float*)d_in[3];
    const float* W2 = (const float*)d_in[4];
    const float* b2 = (const float*)d_in[5];
    float* out = (float*)d_out;

    int n = in_sizes[0] / DIN;
    long long e = (long long)in_sizes[1] / 2;

    int nb_n    = (n + 255) / 256;
    int nb_e    = (int)((e + 255) / 256);
    int nb_scan = (n + SCAN_CHUNK - 1) / SCAN_CHUNK;
    int nb_g    = ((n + 1) / 2 + 255) / 256;
    int nb_a1   = (n * 16 + 255) / 256;
    int nb_a2   = (n * 8 + 255) / 256;

    k_zero_detect<<<nb_n,    256>>>(ei, e, n);
    k_prep       <<<nb_e,    256>>>(ei, e);
    k_scanA      <<<nb_scan, 256>>>(n);
    k_scanC      <<<nb_scan, 256>>>(n, nb_scan);
    k_place      <<<nb_e,    256>>>(e);
    k_gemm1      <<<nb_g,    256>>>(x, W1, n);
    k_agg1       <<<nb_a1,   256>>>(b1, W2, n);
    k_agg2       <<<nb_a2,   256>>>(b2, out, n);
}